// round 10
// baseline (speedup 1.0000x reference)
#include <cuda_runtime.h>
#include <cuda_bf16.h>
#include <cuda_fp16.h>
#include <math.h>
#include <stdint.h>

// ---------------------------------------------------------------------------
// Problem constants
// ---------------------------------------------------------------------------
#define NMAX   50176            // padded (50000 real)
#define EMAX   800000
#define ETMAX  (NMAX + EMAX)
#define F1     128
#define H1     4
#define OC2    32
#define WSTR   68               // padded uint32 row stride for B tiles in SMEM

// ---------------------------------------------------------------------------
// Scratch (device globals)
// ---------------------------------------------------------------------------
__device__ __align__(16) uint32_t g_h1 [NMAX * 64];   // h1 half2-packed (128 cols)
__device__ __align__(16) uint32_t g_o1 [NMAX * 64];   // layer1 out, half2-packed
__device__ __align__(16) uint32_t g_h2 [NMAX * 16];   // h2 half2-packed (32 cols)
__device__ __align__(16) float    g_es1[NMAX * H1];
__device__ __align__(16) float    g_ed1[NMAX * H1];
__device__ __align__(16) float    g_es2[NMAX];
__device__ __align__(16) float    g_ed2[NMAX];
__device__ __align__(16) uint32_t g_w1hi[128 * WSTR]; // W1^T hi, n-major padded
__device__ __align__(16) uint32_t g_w1lo[128 * WSTR];
__device__ __align__(16) uint32_t g_w2hi[32 * WSTR];  // W2^T hi
__device__ __align__(16) uint32_t g_w2lo[32 * WSTR];
__device__ int g_deg[NMAX];
__device__ int g_rowptr[NMAX + 1];
__device__ int g_cursor[NMAX];
__device__ int g_csr_src[ETMAX];
__device__ int g_bsum[64];
__device__ int g_boff[64];
// grid-barrier state (generation-based; safe across graph replays)
__device__ volatile unsigned g_gen;
__device__ unsigned g_cnt;

static inline int cdiv(int a, int b) { return (a + b - 1) / b; }

// ---------------------------------------------------------------------------
// bf16 hi/lo pack helpers
// ---------------------------------------------------------------------------
__device__ __forceinline__ uint32_t pack_bf2(float a, float b) {
    __nv_bfloat16 ha = __float2bfloat16(a), hb = __float2bfloat16(b);
    unsigned short ua = *(unsigned short*)&ha, ub = *(unsigned short*)&hb;
    return (uint32_t)ua | ((uint32_t)ub << 16);
}
__device__ __forceinline__ void split2(float2 v, uint32_t& hi, uint32_t& lo) {
    __nv_bfloat16 h0 = __float2bfloat16(v.x), h1b = __float2bfloat16(v.y);
    unsigned short u0 = *(unsigned short*)&h0, u1 = *(unsigned short*)&h1b;
    hi = (uint32_t)u0 | ((uint32_t)u1 << 16);
    lo = pack_bf2(v.x - __bfloat162float(h0), v.y - __bfloat162float(h1b));
}

// ---------------------------------------------------------------------------
// Single persistent CSR-build kernel (zero + count + scan + finalize + scatter)
// Grid must be fully resident (sized via occupancy API on host).
// ---------------------------------------------------------------------------
__device__ __forceinline__ void grid_barrier(unsigned nb) {
    __threadfence();
    __syncthreads();
    if (threadIdx.x == 0) {
        unsigned gen = g_gen;
        __threadfence();
        if (atomicAdd(&g_cnt, 1u) == nb - 1u) {
            g_cnt = 0u;
            __threadfence();
            g_gen = gen + 1u;
        } else {
            while (g_gen == gen) __nanosleep(20);
            __threadfence();
        }
    }
    __syncthreads();
}

__device__ __forceinline__ int block_detect_i64(const int* ei) {
    int any = 0;
    #pragma unroll 8
    for (int k = 1; k < 128; k += 2) any |= ei[k];
    return (any == 0) ? 1 : 0;
}

__global__ void __launch_bounds__(256)
build_csr_kernel(const int* __restrict__ ei, int E, int n,
                 int* __restrict__ deg, int* __restrict__ rowptr,
                 int* __restrict__ cursor, int* __restrict__ csr_src,
                 int* __restrict__ bsum, int* __restrict__ boff,
                 unsigned nb) {
    __shared__ int s64;
    __shared__ int sh[256];
    __shared__ int sb[64];
    if (threadIdx.x == 0) s64 = block_detect_i64(ei);
    __syncthreads();
    const int tg = blockIdx.x * blockDim.x + threadIdx.x;
    const int stride = gridDim.x * blockDim.x;
    const int ET = E + n;

    // P0: zero degree histogram
    for (int i = tg; i < n; i += stride) deg[i] = 0;
    grid_barrier(nb);

    // P1: count
    for (int i = tg; i < ET; i += stride) {
        int d;
        if (i < E) {
            d = s64 ? (int)((const long long*)ei)[(long long)E + i] : ei[E + i];
        } else {
            d = i - E;
        }
        atomicAdd(&deg[d], 1);
    }
    grid_barrier(nb);

    // P2: per-chunk (1024) inclusive scans -> rowptr[i+1], bsum[chunk]
    const int nchunk = (n + 1023) >> 10;
    for (int c = blockIdx.x; c < nchunk; c += gridDim.x) {
        int base = c << 10;
        int t = threadIdx.x;
        int e0 = base + t * 4;
        int v0 = (e0     < n) ? deg[e0]     : 0;
        int v1 = (e0 + 1 < n) ? deg[e0 + 1] : 0;
        int v2 = (e0 + 2 < n) ? deg[e0 + 2] : 0;
        int v3 = (e0 + 3 < n) ? deg[e0 + 3] : 0;
        int s1 = v0 + v1, s2 = s1 + v2, s3 = s2 + v3;
        sh[t] = s3;
        __syncthreads();
        for (int off = 1; off < 256; off <<= 1) {
            int u = (t >= off) ? sh[t - off] : 0;
            __syncthreads();
            sh[t] += u;
            __syncthreads();
        }
        int excl = sh[t] - s3;
        if (e0     < n) rowptr[e0 + 1] = excl + v0;
        if (e0 + 1 < n) rowptr[e0 + 2] = excl + s1;
        if (e0 + 2 < n) rowptr[e0 + 3] = excl + s2;
        if (e0 + 3 < n) rowptr[e0 + 4] = excl + s3;
        if (t == 255) bsum[c] = sh[255];
        __syncthreads();
    }
    grid_barrier(nb);

    // P3: block 0 scans chunk sums (<=64)
    if (blockIdx.x == 0) {
        int t = threadIdx.x;
        if (t < 64) sb[t] = (t < nchunk) ? bsum[t] : 0;
        __syncthreads();
        #pragma unroll
        for (int off = 1; off < 64; off <<= 1) {
            int u = (t < 64 && t >= off) ? sb[t - off] : 0;
            __syncthreads();
            if (t < 64) sb[t] += u;
            __syncthreads();
        }
        if (t < 64) boff[t] = sb[t];
    }
    grid_barrier(nb);

    // P4: finalize rowptr (+chunk offsets), init cursor
    for (int i = tg; i <= n; i += stride) {
        int v;
        if (i == 0) v = 0;
        else {
            int c = (i - 1) >> 10;
            v = rowptr[i] + (c > 0 ? boff[c - 1] : 0);
        }
        rowptr[i] = v;
        if (i < n) cursor[i] = v;
    }
    grid_barrier(nb);

    // P5: scatter src indices into CSR buckets
    for (int i = tg; i < ET; i += stride) {
        int s, d;
        if (i < E) {
            if (s64) {
                const long long* p = (const long long*)ei;
                s = (int)p[i];
                d = (int)p[(long long)E + i];
            } else {
                s = ei[i];
                d = ei[E + i];
            }
        } else {
            s = i - E;
            d = i - E;
        }
        int p = atomicAdd(&cursor[d], 1);
        csr_src[p] = s;
    }
}

// ---------------------------------------------------------------------------
// W prep: W1[128,128], W2[128,32] -> B^T images (n-major, WSTR-padded), hi/lo
// ---------------------------------------------------------------------------
__global__ void prep_w_kernel(const float* __restrict__ W1,
                              const float* __restrict__ W2,
                              uint32_t* __restrict__ w1hi, uint32_t* __restrict__ w1lo,
                              uint32_t* __restrict__ w2hi, uint32_t* __restrict__ w2lo) {
    int i = blockIdx.x * blockDim.x + threadIdx.x;
    if (i < 128 * 64) {
        int nrow = i >> 6, kp = i & 63;
        float2 v = make_float2(W1[(2 * kp) * 128 + nrow], W1[(2 * kp + 1) * 128 + nrow]);
        uint32_t hi, lo; split2(v, hi, lo);
        w1hi[nrow * WSTR + kp] = hi;
        w1lo[nrow * WSTR + kp] = lo;
    } else if (i < 128 * 64 + 32 * 64) {
        int j = i - 128 * 64;
        int nrow = j >> 6, kp = j & 63;
        float2 v = make_float2(W2[(2 * kp) * 32 + nrow], W2[(2 * kp + 1) * 32 + nrow]);
        uint32_t hi, lo; split2(v, hi, lo);
        w2hi[nrow * WSTR + kp] = hi;
        w2lo[nrow * WSTR + kp] = lo;
    }
}

// ---------------------------------------------------------------------------
// Unified GEMM via mma.sync bf16 hi/lo split + fused attention logits.
// ---------------------------------------------------------------------------
__device__ __forceinline__ void mma_bf16(float& c0, float& c1, float& c2, float& c3,
                                         uint32_t a0, uint32_t a1, uint32_t a2, uint32_t a3,
                                         uint32_t b0, uint32_t b1) {
    asm volatile(
        "mma.sync.aligned.m16n8k16.row.col.f32.bf16.bf16.f32 "
        "{%0,%1,%2,%3}, {%4,%5,%6,%7}, {%8,%9}, {%0,%1,%2,%3};"
        : "+f"(c0), "+f"(c1), "+f"(c2), "+f"(c3)
        : "r"(a0), "r"(a1), "r"(a2), "r"(a3), "r"(b0), "r"(b1));
}

template<int NCOLS, int HEADS, bool HALF_IN>
__global__ void __launch_bounds__(256)
gemm_mma_kernel(const void* __restrict__ Xv,
                const uint32_t* __restrict__ whi,
                const uint32_t* __restrict__ wlo,
                const float* __restrict__ a_src,
                const float* __restrict__ a_dst,
                uint32_t* __restrict__ Hout,      // half2-packed, NCOLS/2 words/row
                float* __restrict__ es, float* __restrict__ ed, int n) {
    constexpr int NT = NCOLS / 8;
    constexpr int WWORDS = NCOLS * WSTR;
    extern __shared__ uint32_t smem_u[];
    uint32_t* sWhi = smem_u;
    uint32_t* sWlo = smem_u + WWORDS;
    float* sAs = (float*)(smem_u + 2 * WWORDS);
    float* sAd = sAs + NCOLS;

    const int tid = threadIdx.x;
    const int w = tid >> 5, lane = tid & 31;
    const int g = lane >> 2, t2 = lane & 3;

    for (int i = tid; i < WWORDS; i += 256) {
        sWhi[i] = whi[i];
        sWlo[i] = wlo[i];
    }
    if (tid < NCOLS) { sAs[tid] = a_src[tid]; sAd[tid] = a_dst[tid]; }
    __syncthreads();

    const int base = blockIdx.x * 128 + w * 16;
    const int r0 = base + g, r1 = base + g + 8;
    const bool v0 = r0 < n, v1 = r1 < n;

    float acc[NT][4];
    #pragma unroll
    for (int nt = 0; nt < NT; nt++)
        #pragma unroll
        for (int j = 0; j < 4; j++) acc[nt][j] = 0.f;

    #pragma unroll
    for (int ks = 0; ks < 8; ks++) {
        const int wi = ks * 8 + t2;               // float2/half2 word index
        float2 f00, f02, f10, f12;
        if (HALF_IN) {
            const uint32_t* x0 = (const uint32_t*)Xv + (size_t)r0 * 64;
            const uint32_t* x1 = (const uint32_t*)Xv + (size_t)r1 * 64;
            uint32_t u00 = v0 ? x0[wi] : 0u, u02 = v0 ? x0[wi + 4] : 0u;
            uint32_t u10 = v1 ? x1[wi] : 0u, u12 = v1 ? x1[wi + 4] : 0u;
            f00 = __half22float2(*(__half2*)&u00);
            f02 = __half22float2(*(__half2*)&u02);
            f10 = __half22float2(*(__half2*)&u10);
            f12 = __half22float2(*(__half2*)&u12);
        } else {
            const float* x0 = (const float*)Xv + (size_t)r0 * 128;
            const float* x1 = (const float*)Xv + (size_t)r1 * 128;
            f00 = v0 ? *(const float2*)&x0[wi * 2]     : make_float2(0.f, 0.f);
            f02 = v0 ? *(const float2*)&x0[wi * 2 + 8] : make_float2(0.f, 0.f);
            f10 = v1 ? *(const float2*)&x1[wi * 2]     : make_float2(0.f, 0.f);
            f12 = v1 ? *(const float2*)&x1[wi * 2 + 8] : make_float2(0.f, 0.f);
        }
        uint32_t ah0, al0, ah1, al1, ah2, al2, ah3, al3;
        split2(f00, ah0, al0);
        split2(f10, ah1, al1);
        split2(f02, ah2, al2);
        split2(f12, ah3, al3);
        #pragma unroll
        for (int nt = 0; nt < NT; nt++) {
            const int bidx = (nt * 8 + g) * WSTR + ks * 8 + t2;
            uint32_t bh0 = sWhi[bidx], bh1 = sWhi[bidx + 4];
            uint32_t bl0 = sWlo[bidx], bl1 = sWlo[bidx + 4];
            mma_bf16(acc[nt][0], acc[nt][1], acc[nt][2], acc[nt][3],
                     ah0, ah1, ah2, ah3, bh0, bh1);
            mma_bf16(acc[nt][0], acc[nt][1], acc[nt][2], acc[nt][3],
                     ah0, ah1, ah2, ah3, bl0, bl1);
            mma_bf16(acc[nt][0], acc[nt][1], acc[nt][2], acc[nt][3],
                     al0, al1, al2, al3, bh0, bh1);
        }
    }

    // Epilogue: write half2-packed H rows + fused per-head logits
    float ss0[HEADS], dd0[HEADS], ss1[HEADS], dd1[HEADS];
    #pragma unroll
    for (int h = 0; h < HEADS; h++) { ss0[h] = dd0[h] = ss1[h] = dd1[h] = 0.f; }
    #pragma unroll
    for (int nt = 0; nt < NT; nt++) {
        const int c = nt * 8 + t2 * 2;
        const int head = nt >> 2;          // 32 cols per head in both layers
        float as0 = sAs[c], as1 = sAs[c + 1];
        float ad0 = sAd[c], ad1 = sAd[c + 1];
        ss0[head] += acc[nt][0] * as0 + acc[nt][1] * as1;
        dd0[head] += acc[nt][0] * ad0 + acc[nt][1] * ad1;
        ss1[head] += acc[nt][2] * as0 + acc[nt][3] * as1;
        dd1[head] += acc[nt][2] * ad0 + acc[nt][3] * ad1;
        const int pidx = nt * 4 + t2;      // half2 word index within row
        if (v0) {
            __half2 p = __floats2half2_rn(acc[nt][0], acc[nt][1]);
            Hout[(size_t)r0 * (NCOLS / 2) + pidx] = *(uint32_t*)&p;
        }
        if (v1) {
            __half2 p = __floats2half2_rn(acc[nt][2], acc[nt][3]);
            Hout[(size_t)r1 * (NCOLS / 2) + pidx] = *(uint32_t*)&p;
        }
    }
    #pragma unroll
    for (int h = 0; h < HEADS; h++) {
        ss0[h] += __shfl_xor_sync(0xFFFFFFFF, ss0[h], 1);
        ss0[h] += __shfl_xor_sync(0xFFFFFFFF, ss0[h], 2);
        dd0[h] += __shfl_xor_sync(0xFFFFFFFF, dd0[h], 1);
        dd0[h] += __shfl_xor_sync(0xFFFFFFFF, dd0[h], 2);
        ss1[h] += __shfl_xor_sync(0xFFFFFFFF, ss1[h], 1);
        ss1[h] += __shfl_xor_sync(0xFFFFFFFF, ss1[h], 2);
        dd1[h] += __shfl_xor_sync(0xFFFFFFFF, dd1[h], 1);
        dd1[h] += __shfl_xor_sync(0xFFFFFFFF, dd1[h], 2);
    }
    if (t2 == 0) {
        if (v0) {
            #pragma unroll
            for (int h = 0; h < HEADS; h++) {
                es[r0 * HEADS + h] = ss0[h];
                ed[r0 * HEADS + h] = dd0[h];
            }
        }
        if (v1) {
            #pragma unroll
            for (int h = 0; h < HEADS; h++) {
                es[r1 * HEADS + h] = ss1[h];
                ed[r1 * HEADS + h] = dd1[h];
            }
        }
    }
}

// ---------------------------------------------------------------------------
// Fused layer-1 aggregation: warp per dst; fp16 gather; writes o1 as fp16.
// ---------------------------------------------------------------------------
__global__ void agg1_kernel(const int* __restrict__ rowptr,
                            const int* __restrict__ csr_src,
                            const uint32_t* __restrict__ Hm,   // half2, 64 words/row
                            const float* __restrict__ es,
                            const float* __restrict__ ed,
                            const float* __restrict__ bias,
                            uint32_t* __restrict__ out, int n) {
    int d = (blockIdx.x * blockDim.x + threadIdx.x) >> 5;
    if (d >= n) return;
    int lane = threadIdx.x & 31;
    int head = lane >> 3;
    float edv = ed[d * H1 + head];
    float a0 = 0.f, a1 = 0.f, a2 = 0.f, a3 = 0.f, den = 0.f;
    int beg = rowptr[d], end = rowptr[d + 1];
    for (int base = beg; base < end; base += 32) {
        int e = base + lane;
        int sidx = (e < end) ? csr_src[e] : 0;
        int cnt = end - base; if (cnt > 32) cnt = 32;
        #pragma unroll 8
        for (int j = 0; j < cnt; j++) {
            int s = __shfl_sync(0xFFFFFFFF, sidx, j);
            float v = es[s * H1 + head] + edv;
            v = v > 0.f ? v : 0.2f * v;
            float ex = __expf(v);
            den += ex;
            uint2 hv = *(const uint2*)&Hm[(size_t)s * 64 + lane * 2];
            float2 p0 = __half22float2(*(__half2*)&hv.x);
            float2 p1 = __half22float2(*(__half2*)&hv.y);
            a0 += p0.x * ex; a1 += p0.y * ex; a2 += p1.x * ex; a3 += p1.y * ex;
        }
    }
    float inv = 1.0f / den;
    float4 bv = *(const float4*)&bias[lane * 4];
    float r0 = a0 * inv + bv.x;
    float r1 = a1 * inv + bv.y;
    float r2 = a2 * inv + bv.z;
    float r3 = a3 * inv + bv.w;
    r0 = r0 > 0.f ? r0 : expm1f(r0);
    r1 = r1 > 0.f ? r1 : expm1f(r1);
    r2 = r2 > 0.f ? r2 : expm1f(r2);
    r3 = r3 > 0.f ? r3 : expm1f(r3);
    __half2 p0 = __floats2half2_rn(r0, r1);
    __half2 p1 = __floats2half2_rn(r2, r3);
    uint2 pw = make_uint2(*(uint32_t*)&p0, *(uint32_t*)&p1);
    *(uint2*)&out[(size_t)d * 64 + lane * 2] = pw;
}

// Fused layer-2 aggregation: HALF-WARP per dst; lane owns 2 cols via one half2.
__global__ void agg2_kernel(const int* __restrict__ rowptr,
                            const int* __restrict__ csr_src,
                            const uint32_t* __restrict__ Hm,   // half2, 16 words/row
                            const float* __restrict__ es,
                            const float* __restrict__ ed,
                            const float* __restrict__ bias,
                            float* __restrict__ out, int n) {
    int d = (blockIdx.x * blockDim.x + threadIdx.x) >> 4;
    if (d >= n) return;
    int sl = threadIdx.x & 15;
    float edv = ed[d];
    float acc0 = 0.f, acc1 = 0.f, den = 0.f;
    int beg = rowptr[d], end = rowptr[d + 1];
    for (int base = beg; base < end; base += 16) {
        int e = base + sl;
        int sidx = (e < end) ? csr_src[e] : 0;
        int cnt = end - base; if (cnt > 16) cnt = 16;
        #pragma unroll 8
        for (int j = 0; j < cnt; j++) {
            int s = __shfl_sync(0xFFFFFFFF, sidx, j, 16);
            float v = es[s] + edv;
            v = v > 0.f ? v : 0.2f * v;
            float ex = __expf(v);
            den += ex;
            uint32_t hv = Hm[(size_t)s * 16 + sl];
            float2 p = __half22float2(*(__half2*)&hv);
            acc0 += p.x * ex; acc1 += p.y * ex;
        }
    }
    float inv = 1.0f / den;
    float2 bv = *(const float2*)&bias[sl * 2];
    *(float2*)&out[(size_t)d * OC2 + sl * 2] =
        make_float2(acc0 * inv + bv.x, acc1 * inv + bv.y);
}

// ---------------------------------------------------------------------------
// Launch — single persistent CSR kernel on s2, overlapping prep_w + gemm1.
// ---------------------------------------------------------------------------
extern "C" void kernel_launch(void* const* d_in, const int* in_sizes, int n_in,
                              void* d_out, int out_size) {
    const float* x      = (const float*)d_in[0];
    const int*   ei     = (const int*)  d_in[1];
    const float* W1     = (const float*)d_in[2];
    const float* a_src1 = (const float*)d_in[3];
    const float* a_dst1 = (const float*)d_in[4];
    const float* b1     = (const float*)d_in[5];
    const float* W2     = (const float*)d_in[6];
    const float* a_src2 = (const float*)d_in[7];
    const float* a_dst2 = (const float*)d_in[8];
    const float* b2     = (const float*)d_in[9];
    float* out = (float*)d_out;

    int n = in_sizes[0] / 128;
    long long ee = in_sizes[1];
    int E = (int)(ee / 2);
    if (E > EMAX) E = (int)(ee / 4);

    float *es1, *ed1, *es2, *ed2;
    uint32_t *h1, *o1, *h2, *w1hi, *w1lo, *w2hi, *w2lo;
    int *deg, *rowptr, *cursor, *csr, *bsum, *boff;
    cudaGetSymbolAddress((void**)&h1,  g_h1);
    cudaGetSymbolAddress((void**)&o1,  g_o1);
    cudaGetSymbolAddress((void**)&h2,  g_h2);
    cudaGetSymbolAddress((void**)&es1, g_es1);
    cudaGetSymbolAddress((void**)&ed1, g_ed1);
    cudaGetSymbolAddress((void**)&es2, g_es2);
    cudaGetSymbolAddress((void**)&ed2, g_ed2);
    cudaGetSymbolAddress((void**)&w1hi, g_w1hi);
    cudaGetSymbolAddress((void**)&w1lo, g_w1lo);
    cudaGetSymbolAddress((void**)&w2hi, g_w2hi);
    cudaGetSymbolAddress((void**)&w2lo, g_w2lo);
    cudaGetSymbolAddress((void**)&deg, g_deg);
    cudaGetSymbolAddress((void**)&rowptr, g_rowptr);
    cudaGetSymbolAddress((void**)&cursor, g_cursor);
    cudaGetSymbolAddress((void**)&csr, g_csr_src);
    cudaGetSymbolAddress((void**)&bsum, g_bsum);
    cudaGetSymbolAddress((void**)&boff, g_boff);

    const int sm1 = (2 * 128 * WSTR + 2 * 128) * 4;
    const int sm2 = (2 * 32 * WSTR + 2 * 32) * 4;
    cudaFuncSetAttribute((const void*)gemm_mma_kernel<128, 4, false>,
                         cudaFuncAttributeMaxDynamicSharedMemorySize, sm1);
    cudaFuncSetAttribute((const void*)gemm_mma_kernel<32, 1, true>,
                         cudaFuncAttributeMaxDynamicSharedMemorySize, sm2);

    // Persistent-grid size: all blocks must be resident (grid barrier safety).
    int dev = 0, nsm = 0, bpm = 0;
    cudaGetDevice(&dev);
    cudaDeviceGetAttribute(&nsm, cudaDevAttrMultiProcessorCount, dev);
    cudaOccupancyMaxActiveBlocksPerMultiprocessor(&bpm, build_csr_kernel, 256, 0);
    if (bpm < 1) bpm = 1;
    unsigned nb = (unsigned)(nsm * bpm);

    // Side stream + fork/join events (host-side objects; created once).
    static cudaStream_t s2 = nullptr;
    static cudaEvent_t evF = nullptr, evJ = nullptr;
    if (s2 == nullptr) {
        cudaStreamCreateWithFlags(&s2, cudaStreamNonBlocking);
        cudaEventCreateWithFlags(&evF, cudaEventDisableTiming);
        cudaEventCreateWithFlags(&evJ, cudaEventDisableTiming);
    }

    // ---- fork: CSR build (1 persistent kernel) concurrent with gemm1 leg ----
    cudaEventRecord(evF, 0);
    cudaStreamWaitEvent(s2, evF, 0);
    build_csr_kernel<<<nb, 256, 0, s2>>>(ei, E, n, deg, rowptr, cursor, csr,
                                         bsum, boff, nb);
    cudaEventRecord(evJ, s2);

    prep_w_kernel<<<cdiv(128 * 64 + 32 * 64, 256), 256>>>(W1, W2, w1hi, w1lo, w2hi, w2lo);
    gemm_mma_kernel<128, 4, false><<<cdiv(n, 128), 256, sm1>>>(
        x, w1hi, w1lo, a_src1, a_dst1, h1, es1, ed1, n);

    // ---- join ----
    cudaStreamWaitEvent(0, evJ, 0);

    agg1_kernel<<<cdiv(n * 32, 256), 256>>>(rowptr, csr, h1, es1, ed1, b1, o1, n);
    gemm_mma_kernel<32, 1, true><<<cdiv(n, 128), 256, sm2>>>(
        o1, w2hi, w2lo, a_src2, a_dst2, h2, es2, ed2, n);
    agg2_kernel<<<cdiv(n * 16, 256), 256>>>(rowptr, csr, h2, es2, ed2, b2, out, n);
}

// round 12
// speedup vs baseline: 1.2109x; 1.2109x over previous
#include <cuda_runtime.h>
#include <cuda_bf16.h>
#include <cuda_fp16.h>
#include <math.h>
#include <stdint.h>

// ---------------------------------------------------------------------------
// Problem constants
// ---------------------------------------------------------------------------
#define NMAX   50176            // padded (50000 real)
#define EMAX   800000
#define ETMAX  (NMAX + EMAX)
#define F1     128
#define H1     4
#define OC2    32
#define WSTR   68               // padded uint32 row stride for B tiles in SMEM
#define SCAN_B 1024

// ---------------------------------------------------------------------------
// Scratch (device globals)
// ---------------------------------------------------------------------------
__device__ __align__(16) uint32_t g_h1 [NMAX * 64];   // h1 half2-packed (128 cols)
__device__ __align__(16) uint32_t g_o1 [NMAX * 64];   // layer1 out, half2-packed
__device__ __align__(16) uint32_t g_h2 [NMAX * 16];   // h2 half2-packed (32 cols)
__device__ __align__(16) float    g_es1[NMAX * H1];
__device__ __align__(16) float    g_ed1[NMAX * H1];
__device__ __align__(16) float    g_es2[NMAX];
__device__ __align__(16) float    g_ed2[NMAX];
__device__ __align__(16) uint32_t g_w1hi[128 * WSTR]; // W1^T hi, n-major padded
__device__ __align__(16) uint32_t g_w1lo[128 * WSTR];
__device__ __align__(16) uint32_t g_w2hi[32 * WSTR];  // W2^T hi
__device__ __align__(16) uint32_t g_w2lo[32 * WSTR];
__device__ int g_deg[NMAX];
__device__ int g_rowptr[NMAX + 1];
__device__ int g_cursor[NMAX];
__device__ int g_csr_src[ETMAX];
__device__ int g_bsum[64];

static inline int cdiv(int a, int b) { return (a + b - 1) / b; }

// ---------------------------------------------------------------------------
// bf16 hi/lo pack helpers
// ---------------------------------------------------------------------------
__device__ __forceinline__ uint32_t pack_bf2(float a, float b) {
    __nv_bfloat16 ha = __float2bfloat16(a), hb = __float2bfloat16(b);
    unsigned short ua = *(unsigned short*)&ha, ub = *(unsigned short*)&hb;
    return (uint32_t)ua | ((uint32_t)ub << 16);
}
__device__ __forceinline__ void split2(float2 v, uint32_t& hi, uint32_t& lo) {
    __nv_bfloat16 h0 = __float2bfloat16(v.x), h1b = __float2bfloat16(v.y);
    unsigned short u0 = *(unsigned short*)&h0, u1 = *(unsigned short*)&h1b;
    hi = (uint32_t)u0 | ((uint32_t)u1 << 16);
    lo = pack_bf2(v.x - __bfloat162float(h0), v.y - __bfloat162float(h1b));
}

// ---------------------------------------------------------------------------
// Preprocessing (proven 5-kernel chain, R8 topology)
// ---------------------------------------------------------------------------
__device__ __forceinline__ int block_detect_i64(const int* ei) {
    int any = 0;
    #pragma unroll 8
    for (int k = 1; k < 128; k += 2) any |= ei[k];
    return (any == 0) ? 1 : 0;
}

__global__ void prep_w_kernel(const float* __restrict__ W1,
                              const float* __restrict__ W2,
                              uint32_t* __restrict__ w1hi, uint32_t* __restrict__ w1lo,
                              uint32_t* __restrict__ w2hi, uint32_t* __restrict__ w2lo) {
    int i = blockIdx.x * blockDim.x + threadIdx.x;
    if (i < 128 * 64) {
        int nrow = i >> 6, kp = i & 63;
        float2 v = make_float2(W1[(2 * kp) * 128 + nrow], W1[(2 * kp + 1) * 128 + nrow]);
        uint32_t hi, lo; split2(v, hi, lo);
        w1hi[nrow * WSTR + kp] = hi;
        w1lo[nrow * WSTR + kp] = lo;
    } else if (i < 128 * 64 + 32 * 64) {
        int j = i - 128 * 64;
        int nrow = j >> 6, kp = j & 63;
        float2 v = make_float2(W2[(2 * kp) * 32 + nrow], W2[(2 * kp + 1) * 32 + nrow]);
        uint32_t hi, lo; split2(v, hi, lo);
        w2hi[nrow * WSTR + kp] = hi;
        w2lo[nrow * WSTR + kp] = lo;
    }
}

__global__ void deg_kernel(const int* __restrict__ ei, int E, int n,
                           int* __restrict__ deg) {
    __shared__ int s64;
    if (threadIdx.x == 0) s64 = block_detect_i64(ei);
    __syncthreads();
    int i = blockIdx.x * blockDim.x + threadIdx.x;
    if (i >= E + n) return;
    int d;
    if (i < E) {
        d = s64 ? (int)((const long long*)ei)[(long long)E + i] : ei[E + i];
    } else {
        d = i - E;
    }
    atomicAdd(&deg[d], 1);
}

__global__ void scan_block_kernel(const int* __restrict__ deg,
                                  int* __restrict__ rowptr,
                                  int* __restrict__ bsum, int n) {
    __shared__ int sh[SCAN_B];
    int i = blockIdx.x * SCAN_B + threadIdx.x;
    int v = (i < n) ? deg[i] : 0;
    sh[threadIdx.x] = v;
    __syncthreads();
    for (int off = 1; off < SCAN_B; off <<= 1) {
        int t = (threadIdx.x >= off) ? sh[threadIdx.x - off] : 0;
        __syncthreads();
        sh[threadIdx.x] += t;
        __syncthreads();
    }
    if (i < n) rowptr[i + 1] = sh[threadIdx.x];   // inclusive, pre-offset
    if (threadIdx.x == SCAN_B - 1) bsum[blockIdx.x] = sh[SCAN_B - 1];
}

__global__ void finalize_rowptr_kernel(int* __restrict__ rowptr,
                                       int* __restrict__ cursor,
                                       const int* __restrict__ bsum,
                                       int n, int nb) {
    __shared__ int sb[64];
    int t = threadIdx.x;
    if (t < 64) sb[t] = (t < nb) ? bsum[t] : 0;
    __syncthreads();
    #pragma unroll
    for (int off = 1; off < 64; off <<= 1) {
        int v = (t < 64 && t >= off) ? sb[t - off] : 0;
        __syncthreads();
        if (t < 64) sb[t] += v;
        __syncthreads();
    }
    int idx = blockIdx.x * blockDim.x + t;
    if (idx > n) return;
    int v;
    if (idx == 0) v = 0;
    else {
        int b = (idx - 1) / SCAN_B;
        v = rowptr[idx] + (b > 0 ? sb[b - 1] : 0);
    }
    rowptr[idx] = v;
    if (idx < n) cursor[idx] = v;
}

__global__ void scatter_kernel(const int* __restrict__ ei, int E, int n,
                               int* __restrict__ cursor,
                               int* __restrict__ csr_src) {
    __shared__ int s64;
    if (threadIdx.x == 0) s64 = block_detect_i64(ei);
    __syncthreads();
    int i = blockIdx.x * blockDim.x + threadIdx.x;
    if (i >= E + n) return;
    int s, d;
    if (i < E) {
        if (s64) {
            const long long* p = (const long long*)ei;
            s = (int)p[i];
            d = (int)p[(long long)E + i];
        } else {
            s = ei[i];
            d = ei[E + i];
        }
    } else {
        s = i - E;
        d = i - E;
    }
    int p = atomicAdd(&cursor[d], 1);
    csr_src[p] = s;
}

// ---------------------------------------------------------------------------
// Unified GEMM via mma.sync bf16 hi/lo split + fused attention logits.
// ---------------------------------------------------------------------------
__device__ __forceinline__ void mma_bf16(float& c0, float& c1, float& c2, float& c3,
                                         uint32_t a0, uint32_t a1, uint32_t a2, uint32_t a3,
                                         uint32_t b0, uint32_t b1) {
    asm volatile(
        "mma.sync.aligned.m16n8k16.row.col.f32.bf16.bf16.f32 "
        "{%0,%1,%2,%3}, {%4,%5,%6,%7}, {%8,%9}, {%0,%1,%2,%3};"
        : "+f"(c0), "+f"(c1), "+f"(c2), "+f"(c3)
        : "r"(a0), "r"(a1), "r"(a2), "r"(a3), "r"(b0), "r"(b1));
}

template<int NCOLS, int HEADS, bool HALF_IN>
__global__ void __launch_bounds__(256)
gemm_mma_kernel(const void* __restrict__ Xv,
                const uint32_t* __restrict__ whi,
                const uint32_t* __restrict__ wlo,
                const float* __restrict__ a_src,
                const float* __restrict__ a_dst,
                uint32_t* __restrict__ Hout,      // half2-packed, NCOLS/2 words/row
                float* __restrict__ es, float* __restrict__ ed, int n) {
    constexpr int NT = NCOLS / 8;
    constexpr int WWORDS = NCOLS * WSTR;
    extern __shared__ uint32_t smem_u[];
    uint32_t* sWhi = smem_u;
    uint32_t* sWlo = smem_u + WWORDS;
    float* sAs = (float*)(smem_u + 2 * WWORDS);
    float* sAd = sAs + NCOLS;

    const int tid = threadIdx.x;
    const int w = tid >> 5, lane = tid & 31;
    const int g = lane >> 2, t2 = lane & 3;

    for (int i = tid; i < WWORDS; i += 256) {
        sWhi[i] = whi[i];
        sWlo[i] = wlo[i];
    }
    if (tid < NCOLS) { sAs[tid] = a_src[tid]; sAd[tid] = a_dst[tid]; }
    __syncthreads();

    const int base = blockIdx.x * 128 + w * 16;
    const int r0 = base + g, r1 = base + g + 8;
    const bool v0 = r0 < n, v1 = r1 < n;

    float acc[NT][4];
    #pragma unroll
    for (int nt = 0; nt < NT; nt++)
        #pragma unroll
        for (int j = 0; j < 4; j++) acc[nt][j] = 0.f;

    #pragma unroll
    for (int ks = 0; ks < 8; ks++) {
        const int wi = ks * 8 + t2;               // float2/half2 word index
        float2 f00, f02, f10, f12;
        if (HALF_IN) {
            const uint32_t* x0 = (const uint32_t*)Xv + (size_t)r0 * 64;
            const uint32_t* x1 = (const uint32_t*)Xv + (size_t)r1 * 64;
            uint32_t u00 = v0 ? x0[wi] : 0u, u02 = v0 ? x0[wi + 4] : 0u;
            uint32_t u10 = v1 ? x1[wi] : 0u, u12 = v1 ? x1[wi + 4] : 0u;
            f00 = __half22float2(*(__half2*)&u00);
            f02 = __half22float2(*(__half2*)&u02);
            f10 = __half22float2(*(__half2*)&u10);
            f12 = __half22float2(*(__half2*)&u12);
        } else {
            const float* x0 = (const float*)Xv + (size_t)r0 * 128;
            const float* x1 = (const float*)Xv + (size_t)r1 * 128;
            f00 = v0 ? *(const float2*)&x0[wi * 2]     : make_float2(0.f, 0.f);
            f02 = v0 ? *(const float2*)&x0[wi * 2 + 8] : make_float2(0.f, 0.f);
            f10 = v1 ? *(const float2*)&x1[wi * 2]     : make_float2(0.f, 0.f);
            f12 = v1 ? *(const float2*)&x1[wi * 2 + 8] : make_float2(0.f, 0.f);
        }
        uint32_t ah0, al0, ah1, al1, ah2, al2, ah3, al3;
        split2(f00, ah0, al0);
        split2(f10, ah1, al1);
        split2(f02, ah2, al2);
        split2(f12, ah3, al3);
        #pragma unroll
        for (int nt = 0; nt < NT; nt++) {
            const int bidx = (nt * 8 + g) * WSTR + ks * 8 + t2;
            uint32_t bh0 = sWhi[bidx], bh1 = sWhi[bidx + 4];
            uint32_t bl0 = sWlo[bidx], bl1 = sWlo[bidx + 4];
            mma_bf16(acc[nt][0], acc[nt][1], acc[nt][2], acc[nt][3],
                     ah0, ah1, ah2, ah3, bh0, bh1);
            mma_bf16(acc[nt][0], acc[nt][1], acc[nt][2], acc[nt][3],
                     ah0, ah1, ah2, ah3, bl0, bl1);
            mma_bf16(acc[nt][0], acc[nt][1], acc[nt][2], acc[nt][3],
                     al0, al1, al2, al3, bh0, bh1);
        }
    }

    // Epilogue: write half2-packed H rows + fused per-head logits
    float ss0[HEADS], dd0[HEADS], ss1[HEADS], dd1[HEADS];
    #pragma unroll
    for (int h = 0; h < HEADS; h++) { ss0[h] = dd0[h] = ss1[h] = dd1[h] = 0.f; }
    #pragma unroll
    for (int nt = 0; nt < NT; nt++) {
        const int c = nt * 8 + t2 * 2;
        const int head = nt >> 2;          // 32 cols per head in both layers
        float as0 = sAs[c], as1 = sAs[c + 1];
        float ad0 = sAd[c], ad1 = sAd[c + 1];
        ss0[head] += acc[nt][0] * as0 + acc[nt][1] * as1;
        dd0[head] += acc[nt][0] * ad0 + acc[nt][1] * ad1;
        ss1[head] += acc[nt][2] * as0 + acc[nt][3] * as1;
        dd1[head] += acc[nt][2] * ad0 + acc[nt][3] * ad1;
        const int pidx = nt * 4 + t2;      // half2 word index within row
        if (v0) {
            __half2 p = __floats2half2_rn(acc[nt][0], acc[nt][1]);
            Hout[(size_t)r0 * (NCOLS / 2) + pidx] = *(uint32_t*)&p;
        }
        if (v1) {
            __half2 p = __floats2half2_rn(acc[nt][2], acc[nt][3]);
            Hout[(size_t)r1 * (NCOLS / 2) + pidx] = *(uint32_t*)&p;
        }
    }
    #pragma unroll
    for (int h = 0; h < HEADS; h++) {
        ss0[h] += __shfl_xor_sync(0xFFFFFFFF, ss0[h], 1);
        ss0[h] += __shfl_xor_sync(0xFFFFFFFF, ss0[h], 2);
        dd0[h] += __shfl_xor_sync(0xFFFFFFFF, dd0[h], 1);
        dd0[h] += __shfl_xor_sync(0xFFFFFFFF, dd0[h], 2);
        ss1[h] += __shfl_xor_sync(0xFFFFFFFF, ss1[h], 1);
        ss1[h] += __shfl_xor_sync(0xFFFFFFFF, ss1[h], 2);
        dd1[h] += __shfl_xor_sync(0xFFFFFFFF, dd1[h], 1);
        dd1[h] += __shfl_xor_sync(0xFFFFFFFF, dd1[h], 2);
    }
    if (t2 == 0) {
        if (v0) {
            #pragma unroll
            for (int h = 0; h < HEADS; h++) {
                es[r0 * HEADS + h] = ss0[h];
                ed[r0 * HEADS + h] = dd0[h];
            }
        }
        if (v1) {
            #pragma unroll
            for (int h = 0; h < HEADS; h++) {
                es[r1 * HEADS + h] = ss1[h];
                ed[r1 * HEADS + h] = dd1[h];
            }
        }
    }
}

// ---------------------------------------------------------------------------
// Layer-1 aggregation, two-phase: issue-bound fix.
// Phase A: each lane owns 1 of 32 edges -> one float4 es load + 4 expf,
// staged in smem. Phase B: broadcast loop = shfl + LDS + LDG.64 + 4 FFMA.
// ---------------------------------------------------------------------------
__global__ void __launch_bounds__(256)
agg1_kernel(const int* __restrict__ rowptr,
            const int* __restrict__ csr_src,
            const uint32_t* __restrict__ Hm,   // half2, 64 words/row
            const float* __restrict__ es,
            const float* __restrict__ ed,
            const float* __restrict__ bias,
            uint32_t* __restrict__ out, int n) {
    __shared__ float sEx[8][32][4];
    int d = (blockIdx.x * blockDim.x + threadIdx.x) >> 5;
    if (d >= n) return;                 // whole warp shares d -> uniform exit
    int wib = threadIdx.x >> 5;
    int lane = threadIdx.x & 31;
    int head = lane >> 3;
    float4 edv = *(const float4*)&ed[d * 4];
    float a0 = 0.f, a1 = 0.f, a2 = 0.f, a3 = 0.f, den = 0.f;
    int beg = rowptr[d], end = rowptr[d + 1];
    for (int base = beg; base < end; base += 32) {
        int e = base + lane;
        int sidx = 0;
        // Phase A: per-lane edge scoring (1 float4 load + 4 expf per edge)
        if (e < end) {
            sidx = csr_src[e];
            float4 esv = *(const float4*)&es[sidx * 4];
            float v0 = esv.x + edv.x; v0 = v0 > 0.f ? v0 : 0.2f * v0;
            float v1 = esv.y + edv.y; v1 = v1 > 0.f ? v1 : 0.2f * v1;
            float v2 = esv.z + edv.z; v2 = v2 > 0.f ? v2 : 0.2f * v2;
            float v3 = esv.w + edv.w; v3 = v3 > 0.f ? v3 : 0.2f * v3;
            sEx[wib][lane][0] = __expf(v0);
            sEx[wib][lane][1] = __expf(v1);
            sEx[wib][lane][2] = __expf(v2);
            sEx[wib][lane][3] = __expf(v3);
        }
        __syncwarp();
        int cnt = end - base; if (cnt > 32) cnt = 32;
        // Phase B: lean broadcast loop
        #pragma unroll 8
        for (int j = 0; j < cnt; j++) {
            int s = __shfl_sync(0xFFFFFFFF, sidx, j);
            float exv = sEx[wib][j][head];          // broadcast within 8-lane group
            den += exv;
            uint2 hv = *(const uint2*)&Hm[(size_t)s * 64 + lane * 2];
            float2 p0 = __half22float2(*(__half2*)&hv.x);
            float2 p1 = __half22float2(*(__half2*)&hv.y);
            a0 += p0.x * exv; a1 += p0.y * exv;
            a2 += p1.x * exv; a3 += p1.y * exv;
        }
        __syncwarp();
    }
    float inv = 1.0f / den;
    float4 bv = *(const float4*)&bias[lane * 4];
    float r0 = a0 * inv + bv.x;
    float r1 = a1 * inv + bv.y;
    float r2 = a2 * inv + bv.z;
    float r3 = a3 * inv + bv.w;
    r0 = r0 > 0.f ? r0 : expm1f(r0);
    r1 = r1 > 0.f ? r1 : expm1f(r1);
    r2 = r2 > 0.f ? r2 : expm1f(r2);
    r3 = r3 > 0.f ? r3 : expm1f(r3);
    __half2 p0 = __floats2half2_rn(r0, r1);
    __half2 p1 = __floats2half2_rn(r2, r3);
    uint2 pw = make_uint2(*(uint32_t*)&p0, *(uint32_t*)&p1);
    *(uint2*)&out[(size_t)d * 64 + lane * 2] = pw;
}

// Layer-2 aggregation, two-phase, half-warp per dst (half-warp-safe masks).
__global__ void __launch_bounds__(256)
agg2_kernel(const int* __restrict__ rowptr,
            const int* __restrict__ csr_src,
            const uint32_t* __restrict__ Hm,   // half2, 16 words/row
            const float* __restrict__ es,
            const float* __restrict__ ed,
            const float* __restrict__ bias,
            float* __restrict__ out, int n) {
    __shared__ float sEx[16][16];
    int d = (blockIdx.x * blockDim.x + threadIdx.x) >> 4;
    if (d >= n) return;                 // half-warp shares d -> uniform exit
    int hw = threadIdx.x >> 4;
    int sl = threadIdx.x & 15;
    unsigned hmask = 0xFFFFu << (threadIdx.x & 16);
    float edv = ed[d];
    float acc0 = 0.f, acc1 = 0.f, den = 0.f;
    int beg = rowptr[d], end = rowptr[d + 1];
    for (int base = beg; base < end; base += 16) {
        int e = base + sl;
        int sidx = 0;
        if (e < end) {
            sidx = csr_src[e];
            float v = es[sidx] + edv;
            v = v > 0.f ? v : 0.2f * v;
            sEx[hw][sl] = __expf(v);
        }
        __syncwarp(hmask);
        int cnt = end - base; if (cnt > 16) cnt = 16;
        #pragma unroll 8
        for (int j = 0; j < cnt; j++) {
            int s = __shfl_sync(hmask, sidx, j, 16);
            float exv = sEx[hw][j];
            den += exv;
            uint32_t hv = Hm[(size_t)s * 16 + sl];
            float2 p = __half22float2(*(__half2*)&hv);
            acc0 += p.x * exv; acc1 += p.y * exv;
        }
        __syncwarp(hmask);
    }
    float inv = 1.0f / den;
    float2 bv = *(const float2*)&bias[sl * 2];
    *(float2*)&out[(size_t)d * OC2 + sl * 2] =
        make_float2(acc0 * inv + bv.x, acc1 * inv + bv.y);
}

// ---------------------------------------------------------------------------
// Launch — R8 topology: 5-kernel CSR chain on s2, overlapping prep_w + gemm1.
// ---------------------------------------------------------------------------
extern "C" void kernel_launch(void* const* d_in, const int* in_sizes, int n_in,
                              void* d_out, int out_size) {
    const float* x      = (const float*)d_in[0];
    const int*   ei     = (const int*)  d_in[1];
    const float* W1     = (const float*)d_in[2];
    const float* a_src1 = (const float*)d_in[3];
    const float* a_dst1 = (const float*)d_in[4];
    const float* b1     = (const float*)d_in[5];
    const float* W2     = (const float*)d_in[6];
    const float* a_src2 = (const float*)d_in[7];
    const float* a_dst2 = (const float*)d_in[8];
    const float* b2     = (const float*)d_in[9];
    float* out = (float*)d_out;

    int n = in_sizes[0] / 128;
    long long ee = in_sizes[1];
    int E = (int)(ee / 2);
    if (E > EMAX) E = (int)(ee / 4);
    int ET = E + n;
    int nblk = cdiv(n, SCAN_B);

    float *es1, *ed1, *es2, *ed2;
    uint32_t *h1, *o1, *h2, *w1hi, *w1lo, *w2hi, *w2lo;
    int *deg, *rowptr, *cursor, *csr, *bsum;
    cudaGetSymbolAddress((void**)&h1,  g_h1);
    cudaGetSymbolAddress((void**)&o1,  g_o1);
    cudaGetSymbolAddress((void**)&h2,  g_h2);
    cudaGetSymbolAddress((void**)&es1, g_es1);
    cudaGetSymbolAddress((void**)&ed1, g_ed1);
    cudaGetSymbolAddress((void**)&es2, g_es2);
    cudaGetSymbolAddress((void**)&ed2, g_ed2);
    cudaGetSymbolAddress((void**)&w1hi, g_w1hi);
    cudaGetSymbolAddress((void**)&w1lo, g_w1lo);
    cudaGetSymbolAddress((void**)&w2hi, g_w2hi);
    cudaGetSymbolAddress((void**)&w2lo, g_w2lo);
    cudaGetSymbolAddress((void**)&deg, g_deg);
    cudaGetSymbolAddress((void**)&rowptr, g_rowptr);
    cudaGetSymbolAddress((void**)&cursor, g_cursor);
    cudaGetSymbolAddress((void**)&csr, g_csr_src);
    cudaGetSymbolAddress((void**)&bsum, g_bsum);

    const int sm1 = (2 * 128 * WSTR + 2 * 128) * 4;
    const int sm2 = (2 * 32 * WSTR + 2 * 32) * 4;
    cudaFuncSetAttribute((const void*)gemm_mma_kernel<128, 4, false>,
                         cudaFuncAttributeMaxDynamicSharedMemorySize, sm1);
    cudaFuncSetAttribute((const void*)gemm_mma_kernel<32, 1, true>,
                         cudaFuncAttributeMaxDynamicSharedMemorySize, sm2);

    // Side stream + fork/join events (host-side objects; created once).
    static cudaStream_t s2 = nullptr;
    static cudaEvent_t evF = nullptr, evJ = nullptr;
    if (s2 == nullptr) {
        cudaStreamCreateWithFlags(&s2, cudaStreamNonBlocking);
        cudaEventCreateWithFlags(&evF, cudaEventDisableTiming);
        cudaEventCreateWithFlags(&evJ, cudaEventDisableTiming);
    }

    // ---- fork: CSR build on s2, concurrent with W prep + gemm1 on main ----
    cudaEventRecord(evF, 0);
    cudaStreamWaitEvent(s2, evF, 0);
    cudaMemsetAsync(deg, 0, (size_t)n * sizeof(int), s2);
    deg_kernel<<<cdiv(ET, 256), 256, 0, s2>>>(ei, E, n, deg);
    scan_block_kernel<<<nblk, SCAN_B, 0, s2>>>(deg, rowptr, bsum, n);
    finalize_rowptr_kernel<<<cdiv(n + 1, 256), 256, 0, s2>>>(rowptr, cursor, bsum, n, nblk);
    scatter_kernel<<<cdiv(ET, 256), 256, 0, s2>>>(ei, E, n, cursor, csr);
    cudaEventRecord(evJ, s2);

    prep_w_kernel<<<cdiv(128 * 64 + 32 * 64, 256), 256>>>(W1, W2, w1hi, w1lo, w2hi, w2lo);
    gemm_mma_kernel<128, 4, false><<<cdiv(n, 128), 256, sm1>>>(
        x, w1hi, w1lo, a_src1, a_dst1, h1, es1, ed1, n);

    // ---- join ----
    cudaStreamWaitEvent(0, evJ, 0);

    agg1_kernel<<<cdiv(n * 32, 256), 256>>>(rowptr, csr, h1, es1, ed1, b1, o1, n);
    gemm_mma_kernel<32, 1, true><<<cdiv(n, 128), 256, sm2>>>(
        o1, w2hi, w2lo, a_src2, a_dst2, h2, es2, ed2, n);
    agg2_kernel<<<cdiv(n * 16, 256), 256>>>(rowptr, csr, h2, es2, ed2, b2, out, n);
}

// round 16
// speedup vs baseline: 1.2209x; 1.0083x over previous
#include <cuda_runtime.h>
#include <cuda_bf16.h>
#include <cuda_fp16.h>
#include <math.h>
#include <stdint.h>

// ---------------------------------------------------------------------------
// Problem constants
// ---------------------------------------------------------------------------
#define NMAX   50176            // padded (50000 real)
#define EMAX   800000
#define ETMAX  (NMAX + EMAX)
#define F1     128
#define H1     4
#define OC2    32
#define WSTR   68               // padded uint32 row stride for B tiles in SMEM
#define SCAN_B 1024

// ---------------------------------------------------------------------------
// Scratch (device globals)
// ---------------------------------------------------------------------------
__device__ __align__(16) uint32_t g_h1 [NMAX * 64];   // h1 half2-packed (128 cols)
__device__ __align__(16) uint32_t g_o1 [NMAX * 64];   // layer1 out, half2-packed
__device__ __align__(16) uint32_t g_h2 [NMAX * 16];   // h2 half2-packed (32 cols)
__device__ __align__(16) float    g_es1[NMAX * H1];
__device__ __align__(16) float    g_ed1[NMAX * H1];
__device__ __align__(16) float    g_es2[NMAX];
__device__ __align__(16) float    g_ed2[NMAX];
__device__ __align__(16) uint32_t g_w1hi[128 * WSTR]; // W1^T hi, n-major padded
__device__ __align__(16) uint32_t g_w1lo[128 * WSTR];
__device__ __align__(16) uint32_t g_w2hi[32 * WSTR];  // W2^T hi
__device__ __align__(16) uint32_t g_w2lo[32 * WSTR];
__device__ int g_deg[NMAX];
__device__ int g_rowptr[NMAX + 1];
__device__ int g_cursor[NMAX];
__device__ int g_csr_src[ETMAX];
__device__ int g_bsum[64];

static inline int cdiv(int a, int b) { return (a + b - 1) / b; }

// ---------------------------------------------------------------------------
// bf16 hi/lo pack helpers
// ---------------------------------------------------------------------------
__device__ __forceinline__ uint32_t pack_bf2(float a, float b) {
    __nv_bfloat16 ha = __float2bfloat16(a), hb = __float2bfloat16(b);
    unsigned short ua = *(unsigned short*)&ha, ub = *(unsigned short*)&hb;
    return (uint32_t)ua | ((uint32_t)ub << 16);
}
__device__ __forceinline__ void split2(float2 v, uint32_t& hi, uint32_t& lo) {
    __nv_bfloat16 h0 = __float2bfloat16(v.x), h1b = __float2bfloat16(v.y);
    unsigned short u0 = *(unsigned short*)&h0, u1 = *(unsigned short*)&h1b;
    hi = (uint32_t)u0 | ((uint32_t)u1 << 16);
    lo = pack_bf2(v.x - __bfloat162float(h0), v.y - __bfloat162float(h1b));
}

// ---------------------------------------------------------------------------
// Preprocessing — ILP-4 edge kernels (4 edges/thread, independent atomics)
// ---------------------------------------------------------------------------
__device__ __forceinline__ int block_detect_i64(const int* ei) {
    int any = 0;
    #pragma unroll 8
    for (int k = 1; k < 128; k += 2) any |= ei[k];
    return (any == 0) ? 1 : 0;
}

__global__ void prep_w_kernel(const float* __restrict__ W1,
                              const float* __restrict__ W2,
                              uint32_t* __restrict__ w1hi, uint32_t* __restrict__ w1lo,
                              uint32_t* __restrict__ w2hi, uint32_t* __restrict__ w2lo) {
    int i = blockIdx.x * blockDim.x + threadIdx.x;
    if (i < 128 * 64) {
        int nrow = i >> 6, kp = i & 63;
        float2 v = make_float2(W1[(2 * kp) * 128 + nrow], W1[(2 * kp + 1) * 128 + nrow]);
        uint32_t hi, lo; split2(v, hi, lo);
        w1hi[nrow * WSTR + kp] = hi;
        w1lo[nrow * WSTR + kp] = lo;
    } else if (i < 128 * 64 + 32 * 64) {
        int j = i - 128 * 64;
        int nrow = j >> 6, kp = j & 63;
        float2 v = make_float2(W2[(2 * kp) * 32 + nrow], W2[(2 * kp + 1) * 32 + nrow]);
        uint32_t hi, lo; split2(v, hi, lo);
        w2hi[nrow * WSTR + kp] = hi;
        w2lo[nrow * WSTR + kp] = lo;
    }
}

// 4 edges per thread: independent dst loads -> 4 concurrent atomics (MLP=4)
__global__ void deg_kernel(const int* __restrict__ ei, int E, int n,
                           int* __restrict__ deg) {
    __shared__ int s64;
    if (threadIdx.x == 0) s64 = block_detect_i64(ei);
    __syncthreads();
    int t = blockIdx.x * blockDim.x + threadIdx.x;
    int ET = E + n;
    int i0 = t * 4;
    if (i0 >= ET) return;
    int d[4];
    int m = ET - i0; if (m > 4) m = 4;
    #pragma unroll
    for (int j = 0; j < 4; j++) {
        int i = i0 + j;
        if (j < m) {
            d[j] = (i < E)
                 ? (s64 ? (int)((const long long*)ei)[(long long)E + i] : ei[E + i])
                 : (i - E);
        }
    }
    #pragma unroll
    for (int j = 0; j < 4; j++)
        if (j < m) atomicAdd(&deg[d[j]], 1);
}

__global__ void scan_block_kernel(const int* __restrict__ deg,
                                  int* __restrict__ rowptr,
                                  int* __restrict__ bsum, int n) {
    __shared__ int sh[SCAN_B];
    int i = blockIdx.x * SCAN_B + threadIdx.x;
    int v = (i < n) ? deg[i] : 0;
    sh[threadIdx.x] = v;
    __syncthreads();
    for (int off = 1; off < SCAN_B; off <<= 1) {
        int t = (threadIdx.x >= off) ? sh[threadIdx.x - off] : 0;
        __syncthreads();
        sh[threadIdx.x] += t;
        __syncthreads();
    }
    if (i < n) rowptr[i + 1] = sh[threadIdx.x];   // inclusive, pre-offset
    if (threadIdx.x == SCAN_B - 1) bsum[blockIdx.x] = sh[SCAN_B - 1];
}

__global__ void finalize_rowptr_kernel(int* __restrict__ rowptr,
                                       int* __restrict__ cursor,
                                       const int* __restrict__ bsum,
                                       int n, int nb) {
    __shared__ int sb[64];
    int t = threadIdx.x;
    if (t < 64) sb[t] = (t < nb) ? bsum[t] : 0;
    __syncthreads();
    #pragma unroll
    for (int off = 1; off < 64; off <<= 1) {
        int v = (t < 64 && t >= off) ? sb[t - off] : 0;
        __syncthreads();
        if (t < 64) sb[t] += v;
        __syncthreads();
    }
    int idx = blockIdx.x * blockDim.x + t;
    if (idx > n) return;
    int v;
    if (idx == 0) v = 0;
    else {
        int b = (idx - 1) / SCAN_B;
        v = rowptr[idx] + (b > 0 ? sb[b - 1] : 0);
    }
    rowptr[idx] = v;
    if (idx < n) cursor[idx] = v;
}

// 4 edges per thread: independent loads + atomics + scatter stores (MLP=4)
__global__ void scatter_kernel(const int* __restrict__ ei, int E, int n,
                               int* __restrict__ cursor,
                               int* __restrict__ csr_src) {
    __shared__ int s64;
    if (threadIdx.x == 0) s64 = block_detect_i64(ei);
    __syncthreads();
    int t = blockIdx.x * blockDim.x + threadIdx.x;
    int ET = E + n;
    int i0 = t * 4;
    if (i0 >= ET) return;
    int s[4], d[4], p[4];
    int m = ET - i0; if (m > 4) m = 4;
    #pragma unroll
    for (int j = 0; j < 4; j++) {
        int i = i0 + j;
        if (j < m) {
            if (i < E) {
                if (s64) {
                    const long long* pp = (const long long*)ei;
                    s[j] = (int)pp[i];
                    d[j] = (int)pp[(long long)E + i];
                } else {
                    s[j] = ei[i];
                    d[j] = ei[E + i];
                }
            } else {
                s[j] = i - E;
                d[j] = i - E;
            }
        }
    }
    #pragma unroll
    for (int j = 0; j < 4; j++)
        if (j < m) p[j] = atomicAdd(&cursor[d[j]], 1);
    #pragma unroll
    for (int j = 0; j < 4; j++)
        if (j < m) csr_src[p[j]] = s[j];
}

// ---------------------------------------------------------------------------
// Unified GEMM via mma.sync bf16 hi/lo split + fused attention logits.
// ---------------------------------------------------------------------------
__device__ __forceinline__ void mma_bf16(float& c0, float& c1, float& c2, float& c3,
                                         uint32_t a0, uint32_t a1, uint32_t a2, uint32_t a3,
                                         uint32_t b0, uint32_t b1) {
    asm volatile(
        "mma.sync.aligned.m16n8k16.row.col.f32.bf16.bf16.f32 "
        "{%0,%1,%2,%3}, {%4,%5,%6,%7}, {%8,%9}, {%0,%1,%2,%3};"
        : "+f"(c0), "+f"(c1), "+f"(c2), "+f"(c3)
        : "r"(a0), "r"(a1), "r"(a2), "r"(a3), "r"(b0), "r"(b1));
}

template<int NCOLS, int HEADS, bool HALF_IN>
__global__ void __launch_bounds__(256)
gemm_mma_kernel(const void* __restrict__ Xv,
                const uint32_t* __restrict__ whi,
                const uint32_t* __restrict__ wlo,
                const float* __restrict__ a_src,
                const float* __restrict__ a_dst,
                uint32_t* __restrict__ Hout,      // half2-packed, NCOLS/2 words/row
                float* __restrict__ es, float* __restrict__ ed, int n) {
    constexpr int NT = NCOLS / 8;
    constexpr int WWORDS = NCOLS * WSTR;
    extern __shared__ uint32_t smem_u[];
    uint32_t* sWhi = smem_u;
    uint32_t* sWlo = smem_u + WWORDS;
    float* sAs = (float*)(smem_u + 2 * WWORDS);
    float* sAd = sAs + NCOLS;

    const int tid = threadIdx.x;
    const int w = tid >> 5, lane = tid & 31;
    const int g = lane >> 2, t2 = lane & 3;

    for (int i = tid; i < WWORDS; i += 256) {
        sWhi[i] = whi[i];
        sWlo[i] = wlo[i];
    }
    if (tid < NCOLS) { sAs[tid] = a_src[tid]; sAd[tid] = a_dst[tid]; }
    __syncthreads();

    const int base = blockIdx.x * 128 + w * 16;
    const int r0 = base + g, r1 = base + g + 8;
    const bool v0 = r0 < n, v1 = r1 < n;

    float acc[NT][4];
    #pragma unroll
    for (int nt = 0; nt < NT; nt++)
        #pragma unroll
        for (int j = 0; j < 4; j++) acc[nt][j] = 0.f;

    #pragma unroll
    for (int ks = 0; ks < 8; ks++) {
        const int wi = ks * 8 + t2;               // float2/half2 word index
        float2 f00, f02, f10, f12;
        if (HALF_IN) {
            const uint32_t* x0 = (const uint32_t*)Xv + (size_t)r0 * 64;
            const uint32_t* x1 = (const uint32_t*)Xv + (size_t)r1 * 64;
            uint32_t u00 = v0 ? x0[wi] : 0u, u02 = v0 ? x0[wi + 4] : 0u;
            uint32_t u10 = v1 ? x1[wi] : 0u, u12 = v1 ? x1[wi + 4] : 0u;
            f00 = __half22float2(*(__half2*)&u00);
            f02 = __half22float2(*(__half2*)&u02);
            f10 = __half22float2(*(__half2*)&u10);
            f12 = __half22float2(*(__half2*)&u12);
        } else {
            const float* x0 = (const float*)Xv + (size_t)r0 * 128;
            const float* x1 = (const float*)Xv + (size_t)r1 * 128;
            f00 = v0 ? *(const float2*)&x0[wi * 2]     : make_float2(0.f, 0.f);
            f02 = v0 ? *(const float2*)&x0[wi * 2 + 8] : make_float2(0.f, 0.f);
            f10 = v1 ? *(const float2*)&x1[wi * 2]     : make_float2(0.f, 0.f);
            f12 = v1 ? *(const float2*)&x1[wi * 2 + 8] : make_float2(0.f, 0.f);
        }
        uint32_t ah0, al0, ah1, al1, ah2, al2, ah3, al3;
        split2(f00, ah0, al0);
        split2(f10, ah1, al1);
        split2(f02, ah2, al2);
        split2(f12, ah3, al3);
        #pragma unroll
        for (int nt = 0; nt < NT; nt++) {
            const int bidx = (nt * 8 + g) * WSTR + ks * 8 + t2;
            uint32_t bh0 = sWhi[bidx], bh1 = sWhi[bidx + 4];
            uint32_t bl0 = sWlo[bidx], bl1 = sWlo[bidx + 4];
            mma_bf16(acc[nt][0], acc[nt][1], acc[nt][2], acc[nt][3],
                     ah0, ah1, ah2, ah3, bh0, bh1);
            mma_bf16(acc[nt][0], acc[nt][1], acc[nt][2], acc[nt][3],
                     ah0, ah1, ah2, ah3, bl0, bl1);
            mma_bf16(acc[nt][0], acc[nt][1], acc[nt][2], acc[nt][3],
                     al0, al1, al2, al3, bh0, bh1);
        }
    }

    // Epilogue: write half2-packed H rows + fused per-head logits
    float ss0[HEADS], dd0[HEADS], ss1[HEADS], dd1[HEADS];
    #pragma unroll
    for (int h = 0; h < HEADS; h++) { ss0[h] = dd0[h] = ss1[h] = dd1[h] = 0.f; }
    #pragma unroll
    for (int nt = 0; nt < NT; nt++) {
        const int c = nt * 8 + t2 * 2;
        const int head = nt >> 2;          // 32 cols per head in both layers
        float as0 = sAs[c], as1 = sAs[c + 1];
        float ad0 = sAd[c], ad1 = sAd[c + 1];
        ss0[head] += acc[nt][0] * as0 + acc[nt][1] * as1;
        dd0[head] += acc[nt][0] * ad0 + acc[nt][1] * ad1;
        ss1[head] += acc[nt][2] * as0 + acc[nt][3] * as1;
        dd1[head] += acc[nt][2] * ad0 + acc[nt][3] * ad1;
        const int pidx = nt * 4 + t2;      // half2 word index within row
        if (v0) {
            __half2 p = __floats2half2_rn(acc[nt][0], acc[nt][1]);
            Hout[(size_t)r0 * (NCOLS / 2) + pidx] = *(uint32_t*)&p;
        }
        if (v1) {
            __half2 p = __floats2half2_rn(acc[nt][2], acc[nt][3]);
            Hout[(size_t)r1 * (NCOLS / 2) + pidx] = *(uint32_t*)&p;
        }
    }
    #pragma unroll
    for (int h = 0; h < HEADS; h++) {
        ss0[h] += __shfl_xor_sync(0xFFFFFFFF, ss0[h], 1);
        ss0[h] += __shfl_xor_sync(0xFFFFFFFF, ss0[h], 2);
        dd0[h] += __shfl_xor_sync(0xFFFFFFFF, dd0[h], 1);
        dd0[h] += __shfl_xor_sync(0xFFFFFFFF, dd0[h], 2);
        ss1[h] += __shfl_xor_sync(0xFFFFFFFF, ss1[h], 1);
        ss1[h] += __shfl_xor_sync(0xFFFFFFFF, ss1[h], 2);
        dd1[h] += __shfl_xor_sync(0xFFFFFFFF, dd1[h], 1);
        dd1[h] += __shfl_xor_sync(0xFFFFFFFF, dd1[h], 2);
    }
    if (t2 == 0) {
        if (v0) {
            #pragma unroll
            for (int h = 0; h < HEADS; h++) {
                es[r0 * HEADS + h] = ss0[h];
                ed[r0 * HEADS + h] = dd0[h];
            }
        }
        if (v1) {
            #pragma unroll
            for (int h = 0; h < HEADS; h++) {
                es[r1 * HEADS + h] = ss1[h];
                ed[r1 * HEADS + h] = dd1[h];
            }
        }
    }
}

// ---------------------------------------------------------------------------
// Layer-1 aggregation, two-phase (validated R11).
// ---------------------------------------------------------------------------
__global__ void __launch_bounds__(256)
agg1_kernel(const int* __restrict__ rowptr,
            const int* __restrict__ csr_src,
            const uint32_t* __restrict__ Hm,   // half2, 64 words/row
            const float* __restrict__ es,
            const float* __restrict__ ed,
            const float* __restrict__ bias,
            uint32_t* __restrict__ out, int n) {
    __shared__ float sEx[8][32][4];
    int d = (blockIdx.x * blockDim.x + threadIdx.x) >> 5;
    if (d >= n) return;                 // whole warp shares d -> uniform exit
    int wib = threadIdx.x >> 5;
    int lane = threadIdx.x & 31;
    int head = lane >> 3;
    float4 edv = *(const float4*)&ed[d * 4];
    float a0 = 0.f, a1 = 0.f, a2 = 0.f, a3 = 0.f, den = 0.f;
    int beg = rowptr[d], end = rowptr[d + 1];
    for (int base = beg; base < end; base += 32) {
        int e = base + lane;
        int sidx = 0;
        // Phase A: per-lane edge scoring (1 float4 load + 4 expf per edge)
        if (e < end) {
            sidx = csr_src[e];
            float4 esv = *(const float4*)&es[sidx * 4];
            float v0 = esv.x + edv.x; v0 = v0 > 0.f ? v0 : 0.2f * v0;
            float v1 = esv.y + edv.y; v1 = v1 > 0.f ? v1 : 0.2f * v1;
            float v2 = esv.z + edv.z; v2 = v2 > 0.f ? v2 : 0.2f * v2;
            float v3 = esv.w + edv.w; v3 = v3 > 0.f ? v3 : 0.2f * v3;
            sEx[wib][lane][0] = __expf(v0);
            sEx[wib][lane][1] = __expf(v1);
            sEx[wib][lane][2] = __expf(v2);
            sEx[wib][lane][3] = __expf(v3);
        }
        __syncwarp();
        int cnt = end - base; if (cnt > 32) cnt = 32;
        // Phase B: lean broadcast loop
        #pragma unroll 8
        for (int j = 0; j < cnt; j++) {
            int s = __shfl_sync(0xFFFFFFFF, sidx, j);
            float exv = sEx[wib][j][head];          // broadcast within 8-lane group
            den += exv;
            uint2 hv = *(const uint2*)&Hm[(size_t)s * 64 + lane * 2];
            float2 p0 = __half22float2(*(__half2*)&hv.x);
            float2 p1 = __half22float2(*(__half2*)&hv.y);
            a0 += p0.x * exv; a1 += p0.y * exv;
            a2 += p1.x * exv; a3 += p1.y * exv;
        }
        __syncwarp();
    }
    float inv = 1.0f / den;
    float4 bv = *(const float4*)&bias[lane * 4];
    float r0 = a0 * inv + bv.x;
    float r1 = a1 * inv + bv.y;
    float r2 = a2 * inv + bv.z;
    float r3 = a3 * inv + bv.w;
    r0 = r0 > 0.f ? r0 : expm1f(r0);
    r1 = r1 > 0.f ? r1 : expm1f(r1);
    r2 = r2 > 0.f ? r2 : expm1f(r2);
    r3 = r3 > 0.f ? r3 : expm1f(r3);
    __half2 p0 = __floats2half2_rn(r0, r1);
    __half2 p1 = __floats2half2_rn(r2, r3);
    uint2 pw = make_uint2(*(uint32_t*)&p0, *(uint32_t*)&p1);
    *(uint2*)&out[(size_t)d * 64 + lane * 2] = pw;
}

// Layer-2 aggregation, two-phase, half-warp per dst (half-warp-safe masks).
__global__ void __launch_bounds__(256)
agg2_kernel(const int* __restrict__ rowptr,
            const int* __restrict__ csr_src,
            const uint32_t* __restrict__ Hm,   // half2, 16 words/row
            const float* __restrict__ es,
            const float* __restrict__ ed,
            const float* __restrict__ bias,
            float* __restrict__ out, int n) {
    __shared__ float sEx[16][16];
    int d = (blockIdx.x * blockDim.x + threadIdx.x) >> 4;
    if (d >= n) return;                 // half-warp shares d -> uniform exit
    int hw = threadIdx.x >> 4;
    int sl = threadIdx.x & 15;
    unsigned hmask = 0xFFFFu << (threadIdx.x & 16);
    float edv = ed[d];
    float acc0 = 0.f, acc1 = 0.f, den = 0.f;
    int beg = rowptr[d], end = rowptr[d + 1];
    for (int base = beg; base < end; base += 16) {
        int e = base + sl;
        int sidx = 0;
        if (e < end) {
            sidx = csr_src[e];
            float v = es[sidx] + edv;
            v = v > 0.f ? v : 0.2f * v;
            sEx[hw][sl] = __expf(v);
        }
        __syncwarp(hmask);
        int cnt = end - base; if (cnt > 16) cnt = 16;
        #pragma unroll 8
        for (int j = 0; j < cnt; j++) {
            int s = __shfl_sync(hmask, sidx, j, 16);
            float exv = sEx[hw][j];
            den += exv;
            uint32_t hv = Hm[(size_t)s * 16 + sl];
            float2 p = __half22float2(*(__half2*)&hv);
            acc0 += p.x * exv; acc1 += p.y * exv;
        }
        __syncwarp(hmask);
    }
    float inv = 1.0f / den;
    float2 bv = *(const float2*)&bias[sl * 2];
    *(float2*)&out[(size_t)d * OC2 + sl * 2] =
        make_float2(acc0 * inv + bv.x, acc1 * inv + bv.y);
}

// ---------------------------------------------------------------------------
// Launch — R8 topology: CSR chain on s2 overlapping prep_w + gemm1.
// ---------------------------------------------------------------------------
extern "C" void kernel_launch(void* const* d_in, const int* in_sizes, int n_in,
                              void* d_out, int out_size) {
    const float* x      = (const float*)d_in[0];
    const int*   ei     = (const int*)  d_in[1];
    const float* W1     = (const float*)d_in[2];
    const float* a_src1 = (const float*)d_in[3];
    const float* a_dst1 = (const float*)d_in[4];
    const float* b1     = (const float*)d_in[5];
    const float* W2     = (const float*)d_in[6];
    const float* a_src2 = (const float*)d_in[7];
    const float* a_dst2 = (const float*)d_in[8];
    const float* b2     = (const float*)d_in[9];
    float* out = (float*)d_out;

    int n = in_sizes[0] / 128;
    long long ee = in_sizes[1];
    int E = (int)(ee / 2);
    if (E > EMAX) E = (int)(ee / 4);
    int ET = E + n;
    int nblk = cdiv(n, SCAN_B);

    float *es1, *ed1, *es2, *ed2;
    uint32_t *h1, *o1, *h2, *w1hi, *w1lo, *w2hi, *w2lo;
    int *deg, *rowptr, *cursor, *csr, *bsum;
    cudaGetSymbolAddress((void**)&h1,  g_h1);
    cudaGetSymbolAddress((void**)&o1,  g_o1);
    cudaGetSymbolAddress((void**)&h2,  g_h2);
    cudaGetSymbolAddress((void**)&es1, g_es1);
    cudaGetSymbolAddress((void**)&ed1, g_ed1);
    cudaGetSymbolAddress((void**)&es2, g_es2);
    cudaGetSymbolAddress((void**)&ed2, g_ed2);
    cudaGetSymbolAddress((void**)&w1hi, g_w1hi);
    cudaGetSymbolAddress((void**)&w1lo, g_w1lo);
    cudaGetSymbolAddress((void**)&w2hi, g_w2hi);
    cudaGetSymbolAddress((void**)&w2lo, g_w2lo);
    cudaGetSymbolAddress((void**)&deg, g_deg);
    cudaGetSymbolAddress((void**)&rowptr, g_rowptr);
    cudaGetSymbolAddress((void**)&cursor, g_cursor);
    cudaGetSymbolAddress((void**)&csr, g_csr_src);
    cudaGetSymbolAddress((void**)&bsum, g_bsum);

    const int sm1 = (2 * 128 * WSTR + 2 * 128) * 4;
    const int sm2 = (2 * 32 * WSTR + 2 * 32) * 4;
    cudaFuncSetAttribute((const void*)gemm_mma_kernel<128, 4, false>,
                         cudaFuncAttributeMaxDynamicSharedMemorySize, sm1);
    cudaFuncSetAttribute((const void*)gemm_mma_kernel<32, 1, true>,
                         cudaFuncAttributeMaxDynamicSharedMemorySize, sm2);

    // Side stream + fork/join events (host-side objects; created once).
    static cudaStream_t s2 = nullptr;
    static cudaEvent_t evF = nullptr, evJ = nullptr;
    if (s2 == nullptr) {
        cudaStreamCreateWithFlags(&s2, cudaStreamNonBlocking);
        cudaEventCreateWithFlags(&evF, cudaEventDisableTiming);
        cudaEventCreateWithFlags(&evJ, cudaEventDisableTiming);
    }

    // ---- fork: CSR build on s2, concurrent with W prep + gemm1 on main ----
    cudaEventRecord(evF, 0);
    cudaStreamWaitEvent(s2, evF, 0);
    cudaMemsetAsync(deg, 0, (size_t)n * sizeof(int), s2);
    deg_kernel<<<cdiv(cdiv(ET, 4), 256), 256, 0, s2>>>(ei, E, n, deg);
    scan_block_kernel<<<nblk, SCAN_B, 0, s2>>>(deg, rowptr, bsum, n);
    finalize_rowptr_kernel<<<cdiv(n + 1, 256), 256, 0, s2>>>(rowptr, cursor, bsum, n, nblk);
    scatter_kernel<<<cdiv(cdiv(ET, 4), 256), 256, 0, s2>>>(ei, E, n, cursor, csr);
    cudaEventRecord(evJ, s2);

    prep_w_kernel<<<cdiv(128 * 64 + 32 * 64, 256), 256>>>(W1, W2, w1hi, w1lo, w2hi, w2lo);
    gemm_mma_kernel<128, 4, false><<<cdiv(n, 128), 256, sm1>>>(
        x, w1hi, w1lo, a_src1, a_dst1, h1, es1, ed1, n);

    // ---- join ----
    cudaStreamWaitEvent(0, evJ, 0);

    agg1_kernel<<<cdiv(n * 32, 256), 256>>>(rowptr, csr, h1, es1, ed1, b1, o1, n);
    gemm_mma_kernel<32, 1, true><<<cdiv(n, 128), 256, sm2>>>(
        o1, w2hi, w2lo, a_src2, a_dst2, h2, es2, ed2, n);
    agg2_kernel<<<cdiv(n * 16, 256), 256>>>(rowptr, csr, h2, es2, ed2, b2, out, n);
}